// round 10
// baseline (speedup 1.0000x reference)
#include <cuda_runtime.h>
#include <cuda_bf16.h>
#include <cuda_fp16.h>
#include <math.h>
#include <stdint.h>

// Problem constants
#define EMBED   512
#define HIDDEN  512
#define VOCAB   32000
#define NLAYERS 2
#define BATCH   32
#define SEQ     64
#define STEPS   (SEQ - 1)          // 63
#define MROWS   (STEPS * BATCH)    // 2016
#define MPAD    2048
#define KPA     1024               // A storage: [Ahi | Alo]
#define KB      512                // B storage: single fp16 copy
#define GUNITS  2048               // 4 gates x 512
#define SCAN_G  256                // scan grid (blocks); all co-resident

// ---------------- scratch (no allocations allowed) ----------------
__device__ __half g_A[(size_t)MPAD * KPA];             // 4.2 MB  [hi|lo]
__device__ __half g_B[(size_t)VOCAB * KB];             // 33 MB   out_w hi
__device__ __half g_BW[(size_t)NLAYERS * GUNITS * KB]; // 4.2 MB  Wx hi
__device__ float  g_X[(size_t)MPAD * GUNITS];          // 16.8 MB x-part preacts
__device__ float  g_hT0[2][HIDDEN * BATCH];            // ping-pong h, transposed [k][b]
__device__ float  g_hT1[2][HIDDEN * BATCH];
__device__ float  g_c0T[HIDDEN * BATCH];
__device__ unsigned g_bar[2];                          // grid-barrier counters (self-resetting)
__device__ unsigned g_fin[2];

__device__ __forceinline__ float sigmoidf_(float x) {
    return 1.0f / (1.0f + expf(-x));
}

// ================= PTX helpers (baseline ISA only) =================
static __device__ __forceinline__ uint32_t smem_u32(const void* p) {
    uint32_t a;
    asm("{ .reg .u64 t; cvta.to.shared.u64 t, %1; cvt.u32.u64 %0, t; }" : "=r"(a) : "l"(p));
    return a;
}
static __device__ __forceinline__ void cp_async16(uint32_t dst, const void* src) {
    asm volatile("cp.async.cg.shared.global [%0], [%1], 16;" :: "r"(dst), "l"(src));
}
#define CP_COMMIT()  asm volatile("cp.async.commit_group;" ::: "memory")
#define CP_WAIT(n)   asm volatile("cp.async.wait_group %0;" :: "n"(n) : "memory")

static __device__ __forceinline__ void ldsm4(uint32_t* r, uint32_t addr) {
    asm volatile("ldmatrix.sync.aligned.m8n8.x4.shared.b16 {%0,%1,%2,%3}, [%4];"
                 : "=r"(r[0]), "=r"(r[1]), "=r"(r[2]), "=r"(r[3]) : "r"(addr));
}
static __device__ __forceinline__ void mma16816(float* c, const uint32_t* a,
                                                uint32_t b0, uint32_t b1) {
    asm volatile("mma.sync.aligned.m16n8k16.row.col.f32.f16.f16.f32 "
                 "{%0,%1,%2,%3}, {%4,%5,%6,%7}, {%8,%9}, {%0,%1,%2,%3};"
                 : "+f"(c[0]), "+f"(c[1]), "+f"(c[2]), "+f"(c[3])
                 : "r"(a[0]), "r"(a[1]), "r"(a[2]), "r"(a[3]), "r"(b0), "r"(b1));
}

// ---------------- init: h0/c0 -> transposed state buffers ----------------
__global__ void init_kernel(const float* __restrict__ features,
                            const float* __restrict__ ihw, const float* __restrict__ ihb,
                            const float* __restrict__ icw, const float* __restrict__ icb) {
    __shared__ float feat[EMBED];
    int b = blockIdx.x;
    for (int i = threadIdx.x; i < EMBED; i += blockDim.x)
        feat[i] = features[b * EMBED + i];
    __syncthreads();

    for (int j = threadIdx.x; j < HIDDEN; j += blockDim.x) {
        float ah = ihb[j];
        float ac = icb[j];
        const float4* wh = (const float4*)(ihw + (size_t)j * EMBED);
        const float4* wc = (const float4*)(icw + (size_t)j * EMBED);
        #pragma unroll 4
        for (int e4 = 0; e4 < EMBED / 4; e4++) {
            float4 h4 = wh[e4];
            float4 c4 = wc[e4];
            const float* f = &feat[e4 * 4];
            ah += f[0]*h4.x + f[1]*h4.y + f[2]*h4.z + f[3]*h4.w;
            ac += f[0]*c4.x + f[1]*c4.y + f[2]*c4.z + f[3]*c4.w;
        }
        g_hT0[0][j * BATCH + b] = ah;
        g_hT1[0][j * BATCH + b] = ah;
        g_c0T[j * BATCH + b]    = ac;
    }
}

// ---------------- conversions ----------------
// out_w -> g_B (hi only, K=512)
__global__ __launch_bounds__(256)
void convB_kernel(const float* __restrict__ w) {
    size_t idx = (size_t)blockIdx.x * blockDim.x + threadIdx.x;
    if (idx >= (size_t)VOCAB * 512) return;
    g_B[idx] = __float2half_rn(w[idx]);
}

// Wx (x-part of gate weights, both layers) -> g_BW (hi only, row stride 512)
// gate row r = g*512 + j ; source Wg[l][j][0:512]
__global__ __launch_bounds__(256)
void convWx_kernel(const float* __restrict__ Wf, const float* __restrict__ Wi,
                   const float* __restrict__ Wo, const float* __restrict__ Wc) {
    size_t idx = (size_t)blockIdx.x * blockDim.x + threadIdx.x;
    if (idx >= (size_t)NLAYERS * GUNITS * 512) return;
    int k = (int)(idx & 511);
    int r = (int)((idx >> 9) & (GUNITS - 1));
    int l = (int)(idx >> 20);              // 2048*512 = 2^20
    int g = r >> 9;
    int j = r & 511;
    const float* W = (g == 0) ? Wf : (g == 1) ? Wi : (g == 2) ? Wo : Wc;
    g_BW[((size_t)l * GUNITS + r) * KB + k] =
        __float2half_rn(W[(size_t)l * HIDDEN * 1024 + (size_t)j * 1024 + k]);
}

// embeddings gather -> g_A (A-style: [hi | lo]); row m = t*32+b
__global__ __launch_bounds__(256)
void embA_kernel(const int* __restrict__ captions, const float* __restrict__ embw) {
    size_t idx = (size_t)blockIdx.x * blockDim.x + threadIdx.x;
    if (idx >= (size_t)MROWS * 512) return;
    int m = (int)(idx >> 9);
    int k = (int)(idx & 511);
    int t = m >> 5, b = m & 31;
    int tok = captions[b * SEQ + t];
    float x = embw[(size_t)tok * EMBED + k];
    __half hi = __float2half_rn(x);
    __half lo = __float2half_rn(x - __half2float(hi));
    size_t base = (size_t)m * KPA;
    g_A[base + k]       = hi;
    g_A[base + 512 + k] = lo;
}

// ---------------- generic split HMMA GEMM ----------------
// C[MPAD x N] = sum over nch A-chunks (64 k each) of A_chunk @ B_chunk^T (+bias)
// B chunk index wraps modulo nchB (B stored single-copy, row stride KB).
#define GBK       64
#define GTILE_B   16384              // 128 rows * 128 B
#define GBUF_B    (2 * GTILE_B)
#define SMEM_DYN  (2 * GBUF_B + 512)

__global__ __launch_bounds__(256)
void gemm_split_kernel(const __half* __restrict__ Bsrc, const float* __restrict__ bias,
                       float* __restrict__ C, int N, int permute, int nch, int nchB) {
    extern __shared__ __align__(128) char sm[];
    const uint32_t smu = smem_u32(sm);
    float* bias_s = (float*)(sm + 2 * GBUF_B);

    const int tid  = threadIdx.x;
    const int wid  = tid >> 5;
    const int lane = tid & 31;
    const int n0 = blockIdx.x * 128;
    const int m0 = blockIdx.y * 128;

    const int warp_m = (wid >> 1) * 32;
    const int warp_n = (wid & 1) * 64;

    if (tid < 128) bias_s[tid] = bias ? bias[n0 + tid] : 0.0f;

    auto load_chunk = [&](int c) {
        const int buf = c & 1;
        const int cb = c & (nchB - 1);
        const uint32_t sA = smu + buf * GBUF_B;
        const uint32_t sB = sA + GTILE_B;
        const __half* Ag = g_A + (size_t)m0 * KPA + c * GBK;
        const __half* Bg = Bsrc + (size_t)n0 * KB + cb * GBK;
        #pragma unroll
        for (int i = 0; i < 4; i++) {
            int idx = i * 256 + tid;
            int r  = idx >> 3;
            int ch = idx & 7;
            uint32_t dst = (uint32_t)(r * 128) + (((uint32_t)(ch ^ (r & 7))) << 4);
            cp_async16(sA + dst, Ag + (size_t)r * KPA + ch * 8);
            cp_async16(sB + dst, Bg + (size_t)r * KB + ch * 8);
        }
        CP_COMMIT();
    };

    float acc[2][8][4];
    #pragma unroll
    for (int mi = 0; mi < 2; mi++)
        #pragma unroll
        for (int ni = 0; ni < 8; ni++)
            #pragma unroll
            for (int q = 0; q < 4; q++) acc[mi][ni][q] = 0.f;

    load_chunk(0);
    load_chunk(1);

    for (int c = 0; c < nch; c++) {
        if (c + 1 < nch) { CP_WAIT(1); } else { CP_WAIT(0); }
        __syncthreads();

        const int buf = c & 1;
        const uint32_t sA = smu + buf * GBUF_B;
        const uint32_t sB = sA + GTILE_B;

        #pragma unroll
        for (int ks = 0; ks < GBK / 16; ks++) {
            uint32_t a[2][4];
            #pragma unroll
            for (int mi = 0; mi < 2; mi++) {
                int row = warp_m + mi * 16 + (lane & 15);
                int kc  = ks * 2 + (lane >> 4);
                uint32_t addr = sA + row * 128 + (((uint32_t)(kc ^ (row & 7))) << 4);
                ldsm4(a[mi], addr);
            }
            uint32_t bfr[4][4];
            #pragma unroll
            for (int nj = 0; nj < 4; nj++) {
                int row = warp_n + nj * 16 + (lane & 7) + ((lane >> 4) << 3);
                int kc  = ks * 2 + ((lane >> 3) & 1);
                uint32_t addr = sB + row * 128 + (((uint32_t)(kc ^ (row & 7))) << 4);
                ldsm4(bfr[nj], addr);
            }
            #pragma unroll
            for (int mi = 0; mi < 2; mi++)
                #pragma unroll
                for (int ni = 0; ni < 8; ni++) {
                    const uint32_t* bp = &bfr[ni >> 1][(ni & 1) * 2];
                    mma16816(acc[mi][ni], a[mi], bp[0], bp[1]);
                }
        }
        __syncthreads();
        if (c + 2 < nch) load_chunk(c + 2);
    }

    #pragma unroll
    for (int mi = 0; mi < 2; mi++) {
        int r0 = m0 + warp_m + mi * 16 + (lane >> 2);
        int r1 = r0 + 8;
        float* orow0 = nullptr;
        float* orow1 = nullptr;
        if (permute) {
            if (r0 < MROWS) {
                int bb = r0 & 31, tt = r0 >> 5;
                orow0 = C + (size_t)(bb * STEPS + tt) * N + n0;
            }
            if (r1 < MROWS) {
                int bb = r1 & 31, tt = r1 >> 5;
                orow1 = C + (size_t)(bb * STEPS + tt) * N + n0;
            }
        } else {
            orow0 = C + (size_t)r0 * N + n0;
            orow1 = C + (size_t)r1 * N + n0;
        }
        #pragma unroll
        for (int ni = 0; ni < 8; ni++) {
            int col = warp_n + ni * 8 + (lane & 3) * 2;
            float b0 = bias_s[col];
            float b1 = bias_s[col + 1];
            if (orow0) {
                float2 v; v.x = acc[mi][ni][0] + b0; v.y = acc[mi][ni][1] + b1;
                *(float2*)&orow0[col] = v;
            }
            if (orow1) {
                float2 v; v.x = acc[mi][ni][2] + b0; v.y = acc[mi][ni][3] + b1;
                *(float2*)&orow1[col] = v;
            }
        }
    }
}

// ---------------- persistent scan: 63 steps of one layer ----------------
// EXACT structure of the round-6 passing kernel: 64-k smem staging chunks.
// Grid = 256 blocks x 128 threads, all co-resident; grid barrier per step.
// Block owns units {2*bid, 2*bid+1} for all 4 gates (8 weight rows, smem-resident).
// Epilogue writes fp16 hi/lo split rows straight into g_A (feeds next GEMM).
__global__ __launch_bounds__(128, 2)
void scan_kernel(const float* __restrict__ Wf, const float* __restrict__ Wi,
                 const float* __restrict__ Wo, const float* __restrict__ Wc,
                 const float* __restrict__ bfv, const float* __restrict__ biv,
                 const float* __restrict__ bov, const float* __restrict__ bcv,
                 const float* __restrict__ X, float* __restrict__ hT,
                 const float* __restrict__ c0T, int layer) {
    __shared__ float w_s[4][2][HIDDEN];              // 16 KB
    __shared__ __align__(16) float h_s[64][BATCH];   // 8 KB staging
    __shared__ float ex_s[4][2][BATCH];              // 1 KB
    __shared__ float bias_s[4][2];

    const int tid = threadIdx.x;
    const int bid = blockIdx.x;
    const int b = tid & 31;
    const int q = tid >> 5;

    // load weight slice (h-part) into smem: rows (g, jj) = W_g[2*bid+jj][512:1024]
    #pragma unroll
    for (int pass = 0; pass < 8; pass++) {
        int g = pass >> 1, jj = pass & 1;
        const float* W = (g == 0) ? Wf : (g == 1) ? Wi : (g == 2) ? Wo : Wc;
        const float* src = W + (size_t)(2 * bid + jj) * 1024 + 512;
        *(float4*)&w_s[g][jj][tid * 4] = *(const float4*)&src[tid * 4];
    }
    if (tid < 8) {
        int g = tid >> 1, jj = tid & 1;
        const float* Bv = (g == 0) ? bfv : (g == 1) ? biv : (g == 2) ? bov : bcv;
        bias_s[g][jj] = Bv[2 * bid + jj];
    }
    float c_reg = 0.f;
    if (q < 2) c_reg = c0T[(2 * bid + q) * BATCH + b];
    __syncthreads();

    const unsigned G = gridDim.x;

    for (int t = 0; t < STEPS; t++) {
        const int p = t & 1;
        const float* hc = hT + p * (HIDDEN * BATCH);
        float* hn = hT + (p ^ 1) * (HIDDEN * BATCH);

        float acc0 = 0.f, acc1 = 0.f;
        for (int cch = 0; cch < 8; cch++) {
            __syncthreads();
            // cooperative stage: 64 k's x 32 b = 2048 floats = 512 float4
            const float4* src = (const float4*)hc + cch * 512;
            float4* dst = (float4*)&h_s[0][0];
            #pragma unroll
            for (int i = 0; i < 4; i++)
                dst[i * 128 + tid] = src[i * 128 + tid];
            __syncthreads();

            const float* wa_base = &w_s[q][0][cch * 64];
            const float* wb_base = &w_s[q][1][cch * 64];
            #pragma unroll
            for (int k = 0; k < 64; k += 4) {
                float h0v = h_s[k + 0][b];
                float h1v = h_s[k + 1][b];
                float h2v = h_s[k + 2][b];
                float h3v = h_s[k + 3][b];
                float4 wa = *(const float4*)&wa_base[k];
                float4 wb = *(const float4*)&wb_base[k];
                acc0 += h0v * wa.x + h1v * wa.y + h2v * wa.z + h3v * wa.w;
                acc1 += h0v * wb.x + h1v * wb.y + h2v * wb.z + h3v * wb.w;
            }
        }
        float2 xr = *(const float2*)&X[(size_t)(t * BATCH + b) * GUNITS + q * 512 + 2 * bid];
        ex_s[q][0][b] = acc0 + bias_s[q][0] + xr.x;
        ex_s[q][1][b] = acc1 + bias_s[q][1] + xr.y;
        __syncthreads();

        if (q < 2) {
            float f  = sigmoidf_(ex_s[0][q][b]);
            float i  = sigmoidf_(ex_s[1][q][b]);
            float o  = sigmoidf_(ex_s[2][q][b]);
            float ct = tanhf    (ex_s[3][q][b]);
            c_reg = f * c_reg + i * ct;
            float h = o * tanhf(c_reg);
            int j = 2 * bid + q;
            hn[j * BATCH + b] = h;
            // fused convA: fp16 hi/lo split row for the downstream GEMM
            __half hhi = __float2half_rn(h);
            __half hlo = __float2half_rn(h - __half2float(hhi));
            size_t ab = (size_t)(t * BATCH + b) * KPA + j;
            g_A[ab]       = hhi;
            g_A[ab + 512] = hlo;
        }
        __syncthreads();

        // grid barrier
        if (tid == 0) {
            __threadfence();
            atomicAdd(&g_bar[layer], 1u);
            unsigned target = (unsigned)(t + 1) * G;
            volatile unsigned* pb = &g_bar[layer];
            while (*pb < target) { __nanosleep(32); }
            __threadfence();
        }
        __syncthreads();
    }

    // reset counters for next launch/replay (last block to finish does it)
    if (tid == 0) {
        unsigned v = atomicAdd(&g_fin[layer], 1u);
        if (v == G - 1) {
            g_bar[layer] = 0;
            g_fin[layer] = 0;
            __threadfence();
        }
    }
}

// ---------------- launch ----------------
extern "C" void kernel_launch(void* const* d_in, const int* in_sizes, int n_in,
                              void* d_out, int out_size) {
    const float* features = (const float*)d_in[0];
    const int*   captions = (const int*)  d_in[1];
    const float* embw     = (const float*)d_in[2];
    const float* Wf       = (const float*)d_in[3];
    const float* bf       = (const float*)d_in[4];
    const float* Wi       = (const float*)d_in[5];
    const float* bi       = (const float*)d_in[6];
    const float* Wc       = (const float*)d_in[7];
    const float* bc       = (const float*)d_in[8];
    const float* Wo       = (const float*)d_in[9];
    const float* bo       = (const float*)d_in[10];
    const float* out_w    = (const float*)d_in[11];
    const float* out_b    = (const float*)d_in[12];
    const float* ihw      = (const float*)d_in[13];
    const float* ihb      = (const float*)d_in[14];
    const float* icw      = (const float*)d_in[15];
    const float* icb      = (const float*)d_in[16];
    float* out = (float*)d_out;

    cudaFuncSetAttribute(gemm_split_kernel,
                         cudaFuncAttributeMaxDynamicSharedMemorySize, SMEM_DYN);

    __half* g_B_ptr;  cudaGetSymbolAddress((void**)&g_B_ptr,  g_B);
    __half* g_BW_ptr; cudaGetSymbolAddress((void**)&g_BW_ptr, g_BW);
    float*  g_X_ptr;  cudaGetSymbolAddress((void**)&g_X_ptr,  g_X);
    float*  g_hT0_p;  cudaGetSymbolAddress((void**)&g_hT0_p,  g_hT0);
    float*  g_hT1_p;  cudaGetSymbolAddress((void**)&g_hT1_p,  g_hT1);
    float*  g_c0T_p;  cudaGetSymbolAddress((void**)&g_c0T_p,  g_c0T);

    // 1. init state
    init_kernel<<<BATCH, 256>>>(features, ihw, ihb, icw, icb);

    // 2. conversions (weights; independent of recurrence)
    convB_kernel<<<(VOCAB * 512 + 255) / 256, 256>>>(out_w);
    convWx_kernel<<<(NLAYERS * GUNITS * 512 + 255) / 256, 256>>>(Wf, Wi, Wo, Wc);
    embA_kernel<<<(MROWS * 512 + 255) / 256, 256>>>(captions, embw);

    // 3. X0 = emb @ Wx0^T  (2-term: A=[hi|lo], B chunk wraps modulo 8)
    {
        dim3 grid(GUNITS / 128, MPAD / 128);  // 16 x 16
        gemm_split_kernel<<<grid, 256, SMEM_DYN>>>(g_BW_ptr, nullptr, g_X_ptr,
                                                   GUNITS, 0, 16, 8);
    }

    // 4. layer-0 scan (persistent; writes g_A hi/lo rows for X1)
    scan_kernel<<<SCAN_G, 128>>>(Wf, Wi, Wo, Wc, bf, bi, bo, bc,
                                 g_X_ptr, g_hT0_p, g_c0T_p, 0);

    // 5. X1 = h0 @ Wx1^T
    {
        dim3 grid(GUNITS / 128, MPAD / 128);
        gemm_split_kernel<<<grid, 256, SMEM_DYN>>>(g_BW_ptr + (size_t)GUNITS * KB,
                                                   nullptr, g_X_ptr, GUNITS, 0, 16, 8);
    }

    // 6. layer-1 scan (writes g_A hi/lo rows for logits)
    scan_kernel<<<SCAN_G, 128>>>(Wf + 512 * 1024, Wi + 512 * 1024,
                                 Wo + 512 * 1024, Wc + 512 * 1024,
                                 bf + 512, bi + 512, bo + 512, bc + 512,
                                 g_X_ptr, g_hT1_p, g_c0T_p, 1);

    // 7. logits = h1 @ out_w^T + out_b  (single-term fp16, permuted store)
    {
        dim3 grid(VOCAB / 128, MPAD / 128);   // 250 x 16
        gemm_split_kernel<<<grid, 256, SMEM_DYN>>>(g_B_ptr, out_b, out,
                                                   VOCAB, 1, 8, 8);
    }
}

// round 12
// speedup vs baseline: 1.5062x; 1.5062x over previous
#include <cuda_runtime.h>
#include <cuda_bf16.h>
#include <cuda_fp16.h>
#include <math.h>
#include <stdint.h>

// Problem constants
#define EMBED   512
#define HIDDEN  512
#define VOCAB   32000
#define NLAYERS 2
#define BATCH   32
#define SEQ     64
#define STEPS   (SEQ - 1)          // 63
#define MROWS   (STEPS * BATCH)    // 2016
#define MPAD    2048
#define KPA     1024               // A storage: [Ahi | Alo]
#define KB      512                // B storage: single fp16 copy
#define GUNITS  2048               // 4 gates x 512
#define SCAN_G  256                // scan grid (blocks); all co-resident
#define NCTR    8                  // split-barrier counters
#define CTRPAD  32                 // 128B line per counter

// ---------------- scratch (no allocations allowed) ----------------
__device__ __half g_A[(size_t)MPAD * KPA];             // 4.2 MB  [hi|lo]
__device__ __half g_B[(size_t)VOCAB * KB];             // 33 MB   out_w hi
__device__ __half g_BW[(size_t)NLAYERS * GUNITS * KB]; // 4.2 MB  Wx hi
__device__ float  g_X[(size_t)MPAD * GUNITS];          // 16.8 MB x-part preacts
__device__ float  g_hT0[2][HIDDEN * BATCH];            // ping-pong h, transposed [k][b]
__device__ float  g_hT1[2][HIDDEN * BATCH];
__device__ float  g_c0T[HIDDEN * BATCH];
__device__ unsigned g_ctr[2][NCTR * CTRPAD];           // split grid-barrier counters
__device__ unsigned g_fin[2];

__device__ __forceinline__ float sigmoidf_(float x) {
    return 1.0f / (1.0f + expf(-x));
}

// ================= PTX helpers (baseline ISA only) =================
static __device__ __forceinline__ uint32_t smem_u32(const void* p) {
    uint32_t a;
    asm("{ .reg .u64 t; cvta.to.shared.u64 t, %1; cvt.u32.u64 %0, t; }" : "=r"(a) : "l"(p));
    return a;
}
static __device__ __forceinline__ void cp_async16(uint32_t dst, const void* src) {
    asm volatile("cp.async.cg.shared.global [%0], [%1], 16;" :: "r"(dst), "l"(src));
}
#define CP_COMMIT()  asm volatile("cp.async.commit_group;" ::: "memory")
#define CP_WAIT(n)   asm volatile("cp.async.wait_group %0;" :: "n"(n) : "memory")

static __device__ __forceinline__ void ldsm4(uint32_t* r, uint32_t addr) {
    asm volatile("ldmatrix.sync.aligned.m8n8.x4.shared.b16 {%0,%1,%2,%3}, [%4];"
                 : "=r"(r[0]), "=r"(r[1]), "=r"(r[2]), "=r"(r[3]) : "r"(addr));
}
static __device__ __forceinline__ void mma16816(float* c, const uint32_t* a,
                                                uint32_t b0, uint32_t b1) {
    asm volatile("mma.sync.aligned.m16n8k16.row.col.f32.f16.f16.f32 "
                 "{%0,%1,%2,%3}, {%4,%5,%6,%7}, {%8,%9}, {%0,%1,%2,%3};"
                 : "+f"(c[0]), "+f"(c[1]), "+f"(c[2]), "+f"(c[3])
                 : "r"(a[0]), "r"(a[1]), "r"(a[2]), "r"(a[3]), "r"(b0), "r"(b1));
}

// ---------------- init: h0/c0 -> transposed state buffers ----------------
__global__ void init_kernel(const float* __restrict__ features,
                            const float* __restrict__ ihw, const float* __restrict__ ihb,
                            const float* __restrict__ icw, const float* __restrict__ icb) {
    __shared__ float feat[EMBED];
    int b = blockIdx.x;
    for (int i = threadIdx.x; i < EMBED; i += blockDim.x)
        feat[i] = features[b * EMBED + i];
    __syncthreads();

    for (int j = threadIdx.x; j < HIDDEN; j += blockDim.x) {
        float ah = ihb[j];
        float ac = icb[j];
        const float4* wh = (const float4*)(ihw + (size_t)j * EMBED);
        const float4* wc = (const float4*)(icw + (size_t)j * EMBED);
        #pragma unroll 4
        for (int e4 = 0; e4 < EMBED / 4; e4++) {
            float4 h4 = wh[e4];
            float4 c4 = wc[e4];
            const float* f = &feat[e4 * 4];
            ah += f[0]*h4.x + f[1]*h4.y + f[2]*h4.z + f[3]*h4.w;
            ac += f[0]*c4.x + f[1]*c4.y + f[2]*c4.z + f[3]*c4.w;
        }
        g_hT0[0][j * BATCH + b] = ah;
        g_hT1[0][j * BATCH + b] = ah;
        g_c0T[j * BATCH + b]    = ac;
    }
}

// ---------------- conversions ----------------
// out_w -> g_B (hi only, K=512); float4-vectorized streaming
__global__ __launch_bounds__(256)
void convB_kernel(const float* __restrict__ w) {
    size_t idx4 = (size_t)blockIdx.x * blockDim.x + threadIdx.x;
    if (idx4 >= (size_t)VOCAB * 512 / 4) return;
    float4 v = ((const float4*)w)[idx4];
    __half2 h01 = __floats2half2_rn(v.x, v.y);
    __half2 h23 = __floats2half2_rn(v.z, v.w);
    __half2* dst = (__half2*)g_B + idx4 * 2;
    dst[0] = h01;
    dst[1] = h23;
}

// Wx (x-part of gate weights, both layers) -> g_BW (hi only, row stride 512)
__global__ __launch_bounds__(256)
void convWx_kernel(const float* __restrict__ Wf, const float* __restrict__ Wi,
                   const float* __restrict__ Wo, const float* __restrict__ Wc) {
    size_t idx = (size_t)blockIdx.x * blockDim.x + threadIdx.x;
    if (idx >= (size_t)NLAYERS * GUNITS * 512) return;
    int k = (int)(idx & 511);
    int r = (int)((idx >> 9) & (GUNITS - 1));
    int l = (int)(idx >> 20);              // 2048*512 = 2^20
    int g = r >> 9;
    int j = r & 511;
    const float* W = (g == 0) ? Wf : (g == 1) ? Wi : (g == 2) ? Wo : Wc;
    g_BW[((size_t)l * GUNITS + r) * KB + k] =
        __float2half_rn(W[(size_t)l * HIDDEN * 1024 + (size_t)j * 1024 + k]);
}

// embeddings gather -> g_A (A-style: [hi | lo]); row m = t*32+b
__global__ __launch_bounds__(256)
void embA_kernel(const int* __restrict__ captions, const float* __restrict__ embw) {
    size_t idx = (size_t)blockIdx.x * blockDim.x + threadIdx.x;
    if (idx >= (size_t)MROWS * 512) return;
    int m = (int)(idx >> 9);
    int k = (int)(idx & 511);
    int t = m >> 5, b = m & 31;
    int tok = captions[b * SEQ + t];
    float x = embw[(size_t)tok * EMBED + k];
    __half hi = __float2half_rn(x);
    __half lo = __float2half_rn(x - __half2float(hi));
    size_t base = (size_t)m * KPA;
    g_A[base + k]       = hi;
    g_A[base + 512 + k] = lo;
}

// ---------------- generic split HMMA GEMM ----------------
// C[MPAD x N] = sum over nch A-chunks (64 k each) of A_chunk @ B_chunk^T (+bias)
// B chunk index wraps modulo nchB (B stored single-copy, row stride KB).
#define GBK       64
#define GTILE_B   16384              // 128 rows * 128 B
#define GBUF_B    (2 * GTILE_B)
#define SMEM_DYN  (2 * GBUF_B + 512)

__global__ __launch_bounds__(256)
void gemm_split_kernel(const __half* __restrict__ Bsrc, const float* __restrict__ bias,
                       float* __restrict__ C, int N, int permute, int nch, int nchB) {
    extern __shared__ __align__(128) char sm[];
    const uint32_t smu = smem_u32(sm);
    float* bias_s = (float*)(sm + 2 * GBUF_B);

    const int tid  = threadIdx.x;
    const int wid  = tid >> 5;
    const int lane = tid & 31;
    const int n0 = blockIdx.x * 128;
    const int m0 = blockIdx.y * 128;

    const int warp_m = (wid >> 1) * 32;
    const int warp_n = (wid & 1) * 64;

    if (tid < 128) bias_s[tid] = bias ? bias[n0 + tid] : 0.0f;

    auto load_chunk = [&](int c) {
        const int buf = c & 1;
        const int cb = c & (nchB - 1);
        const uint32_t sA = smu + buf * GBUF_B;
        const uint32_t sB = sA + GTILE_B;
        const __half* Ag = g_A + (size_t)m0 * KPA + c * GBK;
        const __half* Bg = Bsrc + (size_t)n0 * KB + cb * GBK;
        #pragma unroll
        for (int i = 0; i < 4; i++) {
            int idx = i * 256 + tid;
            int r  = idx >> 3;
            int ch = idx & 7;
            uint32_t dst = (uint32_t)(r * 128) + (((uint32_t)(ch ^ (r & 7))) << 4);
            cp_async16(sA + dst, Ag + (size_t)r * KPA + ch * 8);
            cp_async16(sB + dst, Bg + (size_t)r * KB + ch * 8);
        }
        CP_COMMIT();
    };

    float acc[2][8][4];
    #pragma unroll
    for (int mi = 0; mi < 2; mi++)
        #pragma unroll
        for (int ni = 0; ni < 8; ni++)
            #pragma unroll
            for (int q = 0; q < 4; q++) acc[mi][ni][q] = 0.f;

    load_chunk(0);
    load_chunk(1);

    for (int c = 0; c < nch; c++) {
        if (c + 1 < nch) { CP_WAIT(1); } else { CP_WAIT(0); }
        __syncthreads();

        const int buf = c & 1;
        const uint32_t sA = smu + buf * GBUF_B;
        const uint32_t sB = sA + GTILE_B;

        #pragma unroll
        for (int ks = 0; ks < GBK / 16; ks++) {
            uint32_t a[2][4];
            #pragma unroll
            for (int mi = 0; mi < 2; mi++) {
                int row = warp_m + mi * 16 + (lane & 15);
                int kc  = ks * 2 + (lane >> 4);
                uint32_t addr = sA + row * 128 + (((uint32_t)(kc ^ (row & 7))) << 4);
                ldsm4(a[mi], addr);
            }
            uint32_t bfr[4][4];
            #pragma unroll
            for (int nj = 0; nj < 4; nj++) {
                int row = warp_n + nj * 16 + (lane & 7) + ((lane >> 4) << 3);
                int kc  = ks * 2 + ((lane >> 3) & 1);
                uint32_t addr = sB + row * 128 + (((uint32_t)(kc ^ (row & 7))) << 4);
                ldsm4(bfr[nj], addr);
            }
            #pragma unroll
            for (int mi = 0; mi < 2; mi++)
                #pragma unroll
                for (int ni = 0; ni < 8; ni++) {
                    const uint32_t* bp = &bfr[ni >> 1][(ni & 1) * 2];
                    mma16816(acc[mi][ni], a[mi], bp[0], bp[1]);
                }
        }
        __syncthreads();
        if (c + 2 < nch) load_chunk(c + 2);
    }

    #pragma unroll
    for (int mi = 0; mi < 2; mi++) {
        int r0 = m0 + warp_m + mi * 16 + (lane >> 2);
        int r1 = r0 + 8;
        float* orow0 = nullptr;
        float* orow1 = nullptr;
        if (permute) {
            if (r0 < MROWS) {
                int bb = r0 & 31, tt = r0 >> 5;
                orow0 = C + (size_t)(bb * STEPS + tt) * N + n0;
            }
            if (r1 < MROWS) {
                int bb = r1 & 31, tt = r1 >> 5;
                orow1 = C + (size_t)(bb * STEPS + tt) * N + n0;
            }
        } else {
            orow0 = C + (size_t)r0 * N + n0;
            orow1 = C + (size_t)r1 * N + n0;
        }
        #pragma unroll
        for (int ni = 0; ni < 8; ni++) {
            int col = warp_n + ni * 8 + (lane & 3) * 2;
            float b0 = bias_s[col];
            float b1 = bias_s[col + 1];
            if (orow0) {
                float2 v; v.x = acc[mi][ni][0] + b0; v.y = acc[mi][ni][1] + b1;
                *(float2*)&orow0[col] = v;
            }
            if (orow1) {
                float2 v; v.x = acc[mi][ni][2] + b0; v.y = acc[mi][ni][3] + b1;
                *(float2*)&orow1[col] = v;
            }
        }
    }
}

// ---------------- persistent scan: 63 steps of one layer ----------------
// Compute identical to the round-6/round-10 passing kernel.
// Grid barrier v2: 8 padded counters (bid%8), 8 threads poll one each —
// arrival serialization 256->32 per L2 line, polling spread over 8 lines.
__global__ __launch_bounds__(128, 2)
void scan_kernel(const float* __restrict__ Wf, const float* __restrict__ Wi,
                 const float* __restrict__ Wo, const float* __restrict__ Wc,
                 const float* __restrict__ bfv, const float* __restrict__ biv,
                 const float* __restrict__ bov, const float* __restrict__ bcv,
                 const float* __restrict__ X, float* __restrict__ hT,
                 const float* __restrict__ c0T, int layer) {
    __shared__ float w_s[4][2][HIDDEN];              // 16 KB
    __shared__ __align__(16) float h_s[64][BATCH];   // 8 KB staging
    __shared__ float ex_s[4][2][BATCH];              // 1 KB
    __shared__ float bias_s[4][2];

    const int tid = threadIdx.x;
    const int bid = blockIdx.x;
    const int b = tid & 31;
    const int q = tid >> 5;

    // load weight slice (h-part) into smem: rows (g, jj) = W_g[2*bid+jj][512:1024]
    #pragma unroll
    for (int pass = 0; pass < 8; pass++) {
        int g = pass >> 1, jj = pass & 1;
        const float* W = (g == 0) ? Wf : (g == 1) ? Wi : (g == 2) ? Wo : Wc;
        const float* src = W + (size_t)(2 * bid + jj) * 1024 + 512;
        *(float4*)&w_s[g][jj][tid * 4] = *(const float4*)&src[tid * 4];
    }
    if (tid < 8) {
        int g = tid >> 1, jj = tid & 1;
        const float* Bv = (g == 0) ? bfv : (g == 1) ? biv : (g == 2) ? bov : bcv;
        bias_s[g][jj] = Bv[2 * bid + jj];
    }
    float c_reg = 0.f;
    if (q < 2) c_reg = c0T[(2 * bid + q) * BATCH + b];
    __syncthreads();

    const unsigned G = gridDim.x;
    const unsigned per_ctr = G / NCTR;   // 32 arrivals per counter per step

    for (int t = 0; t < STEPS; t++) {
        const int p = t & 1;
        const float* hc = hT + p * (HIDDEN * BATCH);
        float* hn = hT + (p ^ 1) * (HIDDEN * BATCH);

        float acc0 = 0.f, acc1 = 0.f;
        for (int cch = 0; cch < 8; cch++) {
            __syncthreads();
            // cooperative stage: 64 k's x 32 b = 2048 floats = 512 float4
            const float4* src = (const float4*)hc + cch * 512;
            float4* dst = (float4*)&h_s[0][0];
            #pragma unroll
            for (int i = 0; i < 4; i++)
                dst[i * 128 + tid] = src[i * 128 + tid];
            __syncthreads();

            const float* wa_base = &w_s[q][0][cch * 64];
            const float* wb_base = &w_s[q][1][cch * 64];
            #pragma unroll
            for (int k = 0; k < 64; k += 4) {
                float h0v = h_s[k + 0][b];
                float h1v = h_s[k + 1][b];
                float h2v = h_s[k + 2][b];
                float h3v = h_s[k + 3][b];
                float4 wa = *(const float4*)&wa_base[k];
                float4 wb = *(const float4*)&wb_base[k];
                acc0 += h0v * wa.x + h1v * wa.y + h2v * wa.z + h3v * wa.w;
                acc1 += h0v * wb.x + h1v * wb.y + h2v * wb.z + h3v * wb.w;
            }
        }
        float2 xr = *(const float2*)&X[(size_t)(t * BATCH + b) * GUNITS + q * 512 + 2 * bid];
        ex_s[q][0][b] = acc0 + bias_s[q][0] + xr.x;
        ex_s[q][1][b] = acc1 + bias_s[q][1] + xr.y;
        __syncthreads();

        if (q < 2) {
            float f  = sigmoidf_(ex_s[0][q][b]);
            float i  = sigmoidf_(ex_s[1][q][b]);
            float o  = sigmoidf_(ex_s[2][q][b]);
            float ct = tanhf    (ex_s[3][q][b]);
            c_reg = f * c_reg + i * ct;
            float h = o * tanhf(c_reg);
            int j = 2 * bid + q;
            hn[j * BATCH + b] = h;
            // fused convA: fp16 hi/lo split row for the downstream GEMM
            __half hhi = __float2half_rn(h);
            __half hlo = __float2half_rn(h - __half2float(hhi));
            size_t ab = (size_t)(t * BATCH + b) * KPA + j;
            g_A[ab]       = hhi;
            g_A[ab + 512] = hlo;
        }
        __syncthreads();

        // grid barrier v2: split counters
        if (tid == 0) {
            __threadfence();
            atomicAdd(&g_ctr[layer][(bid & (NCTR - 1)) * CTRPAD], 1u);
        }
        if (tid < NCTR) {
            unsigned target = (unsigned)(t + 1) * per_ctr;
            volatile unsigned* pc = &g_ctr[layer][tid * CTRPAD];
            while (*pc < target) { __nanosleep(32); }
            __threadfence();
        }
        __syncthreads();
    }

    // reset counters for next launch/replay (last block to finish does it)
    if (tid == 0) {
        unsigned v = atomicAdd(&g_fin[layer], 1u);
        if (v == G - 1) {
            #pragma unroll
            for (int i = 0; i < NCTR; i++)
                g_ctr[layer][i * CTRPAD] = 0;
            g_fin[layer] = 0;
            __threadfence();
        }
    }
}

// ---------------- launch ----------------
extern "C" void kernel_launch(void* const* d_in, const int* in_sizes, int n_in,
                              void* d_out, int out_size) {
    const float* features = (const float*)d_in[0];
    const int*   captions = (const int*)  d_in[1];
    const float* embw     = (const float*)d_in[2];
    const float* Wf       = (const float*)d_in[3];
    const float* bf       = (const float*)d_in[4];
    const float* Wi       = (const float*)d_in[5];
    const float* bi       = (const float*)d_in[6];
    const float* Wc       = (const float*)d_in[7];
    const float* bc       = (const float*)d_in[8];
    const float* Wo       = (const float*)d_in[9];
    const float* bo       = (const float*)d_in[10];
    const float* out_w    = (const float*)d_in[11];
    const float* out_b    = (const float*)d_in[12];
    const float* ihw      = (const float*)d_in[13];
    const float* ihb      = (const float*)d_in[14];
    const float* icw      = (const float*)d_in[15];
    const float* icb      = (const float*)d_in[16];
    float* out = (float*)d_out;

    cudaFuncSetAttribute(gemm_split_kernel,
                         cudaFuncAttributeMaxDynamicSharedMemorySize, SMEM_DYN);

    __half* g_B_ptr;  cudaGetSymbolAddress((void**)&g_B_ptr,  g_B);
    __half* g_BW_ptr; cudaGetSymbolAddress((void**)&g_BW_ptr, g_BW);
    float*  g_X_ptr;  cudaGetSymbolAddress((void**)&g_X_ptr,  g_X);
    float*  g_hT0_p;  cudaGetSymbolAddress((void**)&g_hT0_p,  g_hT0);
    float*  g_hT1_p;  cudaGetSymbolAddress((void**)&g_hT1_p,  g_hT1);
    float*  g_c0T_p;  cudaGetSymbolAddress((void**)&g_c0T_p,  g_c0T);

    // 1. init state
    init_kernel<<<BATCH, 256>>>(features, ihw, ihb, icw, icb);

    // 2. conversions (weights; independent of recurrence)
    convB_kernel<<<(VOCAB * 512 / 4 + 255) / 256, 256>>>(out_w);
    convWx_kernel<<<(NLAYERS * GUNITS * 512 + 255) / 256, 256>>>(Wf, Wi, Wo, Wc);
    embA_kernel<<<(MROWS * 512 + 255) / 256, 256>>>(captions, embw);

    // 3. X0 = emb @ Wx0^T  (2-term: A=[hi|lo], B chunk wraps modulo 8)
    {
        dim3 grid(GUNITS / 128, MPAD / 128);  // 16 x 16
        gemm_split_kernel<<<grid, 256, SMEM_DYN>>>(g_BW_ptr, nullptr, g_X_ptr,
                                                   GUNITS, 0, 16, 8);
    }

    // 4. layer-0 scan (persistent; writes g_A hi/lo rows for X1)
    scan_kernel<<<SCAN_G, 128>>>(Wf, Wi, Wo, Wc, bf, bi, bo, bc,
                                 g_X_ptr, g_hT0_p, g_c0T_p, 0);

    // 5. X1 = h0 @ Wx1^T
    {
        dim3 grid(GUNITS / 128, MPAD / 128);
        gemm_split_kernel<<<grid, 256, SMEM_DYN>>>(g_BW_ptr + (size_t)GUNITS * KB,
                                                   nullptr, g_X_ptr, GUNITS, 0, 16, 8);
    }

    // 6. layer-1 scan (writes g_A hi/lo rows for logits)
    scan_kernel<<<SCAN_G, 128>>>(Wf + 512 * 1024, Wi + 512 * 1024,
                                 Wo + 512 * 1024, Wc + 512 * 1024,
                                 bf + 512, bi + 512, bo + 512, bc + 512,
                                 g_X_ptr, g_hT1_p, g_c0T_p, 1);

    // 7. logits = h1 @ out_w^T + out_b  (single-term fp16, permuted store)
    {
        dim3 grid(VOCAB / 128, MPAD / 128);   // 250 x 16
        gemm_split_kernel<<<grid, 256, SMEM_DYN>>>(g_B_ptr, out_b, out,
                                                   VOCAB, 1, 8, 8);
    }
}

// round 13
// speedup vs baseline: 1.6662x; 1.1062x over previous
#include <cuda_runtime.h>
#include <cuda_bf16.h>
#include <cuda_fp16.h>
#include <math.h>
#include <stdint.h>

// Problem constants
#define EMBED   512
#define HIDDEN  512
#define VOCAB   32000
#define NLAYERS 2
#define BATCH   32
#define SEQ     64
#define STEPS   (SEQ - 1)          // 63
#define MROWS   (STEPS * BATCH)    // 2016
#define MPAD    2048
#define KPA     1024               // A storage: [Ahi | Alo]
#define KB      512                // B storage: single fp16 copy
#define GUNITS  2048               // 4 gates x 512
#define SCAN_G  256                // scan grid (blocks); all co-resident
#define NCTR    8                  // split-barrier counters
#define CTRPAD  32                 // 128B line per counter

// ---------------- scratch (no allocations allowed) ----------------
__device__ __half g_A[(size_t)MPAD * KPA];             // 4.2 MB  [hi|lo]
__device__ __half g_B[(size_t)VOCAB * KB];             // 33 MB   out_w hi
__device__ __half g_BW[(size_t)NLAYERS * GUNITS * KB]; // 4.2 MB  Wx hi
__device__ float  g_X[(size_t)MPAD * GUNITS];          // 16.8 MB x-part preacts
__device__ float  g_hT0[2][HIDDEN * BATCH];            // ping-pong h, transposed [k][b]
__device__ float  g_hT1[2][HIDDEN * BATCH];
__device__ float  g_c0T[HIDDEN * BATCH];
__device__ unsigned g_ctr[2][NCTR * CTRPAD];           // split grid-barrier counters
__device__ unsigned g_fin[2];

__device__ __forceinline__ float sigmoidf_(float x) {
    return 1.0f / (1.0f + expf(-x));
}

// ================= PTX helpers (baseline ISA only) =================
static __device__ __forceinline__ uint32_t smem_u32(const void* p) {
    uint32_t a;
    asm("{ .reg .u64 t; cvta.to.shared.u64 t, %1; cvt.u32.u64 %0, t; }" : "=r"(a) : "l"(p));
    return a;
}
static __device__ __forceinline__ void cp_async16(uint32_t dst, const void* src) {
    asm volatile("cp.async.cg.shared.global [%0], [%1], 16;" :: "r"(dst), "l"(src));
}
#define CP_COMMIT()  asm volatile("cp.async.commit_group;" ::: "memory")
#define CP_WAIT(n)   asm volatile("cp.async.wait_group %0;" :: "n"(n) : "memory")

static __device__ __forceinline__ void ldsm4(uint32_t* r, uint32_t addr) {
    asm volatile("ldmatrix.sync.aligned.m8n8.x4.shared.b16 {%0,%1,%2,%3}, [%4];"
                 : "=r"(r[0]), "=r"(r[1]), "=r"(r[2]), "=r"(r[3]) : "r"(addr));
}
static __device__ __forceinline__ void mma16816(float* c, const uint32_t* a,
                                                uint32_t b0, uint32_t b1) {
    asm volatile("mma.sync.aligned.m16n8k16.row.col.f32.f16.f16.f32 "
                 "{%0,%1,%2,%3}, {%4,%5,%6,%7}, {%8,%9}, {%0,%1,%2,%3};"
                 : "+f"(c[0]), "+f"(c[1]), "+f"(c[2]), "+f"(c[3])
                 : "r"(a[0]), "r"(a[1]), "r"(a[2]), "r"(a[3]), "r"(b0), "r"(b1));
}

// ---------------- init: h0/c0 -> transposed state buffers ----------------
__global__ void init_kernel(const float* __restrict__ features,
                            const float* __restrict__ ihw, const float* __restrict__ ihb,
                            const float* __restrict__ icw, const float* __restrict__ icb) {
    __shared__ float feat[EMBED];
    int b = blockIdx.x;
    for (int i = threadIdx.x; i < EMBED; i += blockDim.x)
        feat[i] = features[b * EMBED + i];
    __syncthreads();

    for (int j = threadIdx.x; j < HIDDEN; j += blockDim.x) {
        float ah = ihb[j];
        float ac = icb[j];
        const float4* wh = (const float4*)(ihw + (size_t)j * EMBED);
        const float4* wc = (const float4*)(icw + (size_t)j * EMBED);
        #pragma unroll 4
        for (int e4 = 0; e4 < EMBED / 4; e4++) {
            float4 h4 = wh[e4];
            float4 c4 = wc[e4];
            const float* f = &feat[e4 * 4];
            ah += f[0]*h4.x + f[1]*h4.y + f[2]*h4.z + f[3]*h4.w;
            ac += f[0]*c4.x + f[1]*c4.y + f[2]*c4.z + f[3]*c4.w;
        }
        g_hT0[0][j * BATCH + b] = ah;
        g_hT1[0][j * BATCH + b] = ah;
        g_c0T[j * BATCH + b]    = ac;
    }
}

// ---------------- conversions ----------------
// out_w -> g_B (hi only, K=512); float4-vectorized streaming
__global__ __launch_bounds__(256)
void convB_kernel(const float* __restrict__ w) {
    size_t idx4 = (size_t)blockIdx.x * blockDim.x + threadIdx.x;
    if (idx4 >= (size_t)VOCAB * 512 / 4) return;
    float4 v = ((const float4*)w)[idx4];
    __half2 h01 = __floats2half2_rn(v.x, v.y);
    __half2 h23 = __floats2half2_rn(v.z, v.w);
    __half2* dst = (__half2*)g_B + idx4 * 2;
    dst[0] = h01;
    dst[1] = h23;
}

// Wx (x-part of gate weights, both layers) -> g_BW (hi only, row stride 512)
__global__ __launch_bounds__(256)
void convWx_kernel(const float* __restrict__ Wf, const float* __restrict__ Wi,
                   const float* __restrict__ Wo, const float* __restrict__ Wc) {
    size_t idx = (size_t)blockIdx.x * blockDim.x + threadIdx.x;
    if (idx >= (size_t)NLAYERS * GUNITS * 512) return;
    int k = (int)(idx & 511);
    int r = (int)((idx >> 9) & (GUNITS - 1));
    int l = (int)(idx >> 20);              // 2048*512 = 2^20
    int g = r >> 9;
    int j = r & 511;
    const float* W = (g == 0) ? Wf : (g == 1) ? Wi : (g == 2) ? Wo : Wc;
    g_BW[((size_t)l * GUNITS + r) * KB + k] =
        __float2half_rn(W[(size_t)l * HIDDEN * 1024 + (size_t)j * 1024 + k]);
}

// embeddings gather -> g_A (A-style: [hi | lo]); row m = t*32+b
__global__ __launch_bounds__(256)
void embA_kernel(const int* __restrict__ captions, const float* __restrict__ embw) {
    size_t idx = (size_t)blockIdx.x * blockDim.x + threadIdx.x;
    if (idx >= (size_t)MROWS * 512) return;
    int m = (int)(idx >> 9);
    int k = (int)(idx & 511);
    int t = m >> 5, b = m & 31;
    int tok = captions[b * SEQ + t];
    float x = embw[(size_t)tok * EMBED + k];
    __half hi = __float2half_rn(x);
    __half lo = __float2half_rn(x - __half2float(hi));
    size_t base = (size_t)m * KPA;
    g_A[base + k]       = hi;
    g_A[base + 512 + k] = lo;
}

// ---------------- generic split HMMA GEMM ----------------
// C[MPAD x N] = sum over nch A-chunks (64 k each) of A_chunk @ B_chunk^T (+bias)
// B chunk index wraps modulo nchB (B stored single-copy, row stride KB).
#define GBK       64
#define GTILE_B   16384              // 128 rows * 128 B
#define GBUF_B    (2 * GTILE_B)
#define SMEM_DYN  (2 * GBUF_B + 512)

__global__ __launch_bounds__(256)
void gemm_split_kernel(const __half* __restrict__ Bsrc, const float* __restrict__ bias,
                       float* __restrict__ C, int N, int permute, int nch, int nchB) {
    extern __shared__ __align__(128) char sm[];
    const uint32_t smu = smem_u32(sm);
    float* bias_s = (float*)(sm + 2 * GBUF_B);

    const int tid  = threadIdx.x;
    const int wid  = tid >> 5;
    const int lane = tid & 31;
    const int n0 = blockIdx.x * 128;
    const int m0 = blockIdx.y * 128;

    const int warp_m = (wid >> 1) * 32;
    const int warp_n = (wid & 1) * 64;

    if (tid < 128) bias_s[tid] = bias ? bias[n0 + tid] : 0.0f;

    auto load_chunk = [&](int c) {
        const int buf = c & 1;
        const int cb = c & (nchB - 1);
        const uint32_t sA = smu + buf * GBUF_B;
        const uint32_t sB = sA + GTILE_B;
        const __half* Ag = g_A + (size_t)m0 * KPA + c * GBK;
        const __half* Bg = Bsrc + (size_t)n0 * KB + cb * GBK;
        #pragma unroll
        for (int i = 0; i < 4; i++) {
            int idx = i * 256 + tid;
            int r  = idx >> 3;
            int ch = idx & 7;
            uint32_t dst = (uint32_t)(r * 128) + (((uint32_t)(ch ^ (r & 7))) << 4);
            cp_async16(sA + dst, Ag + (size_t)r * KPA + ch * 8);
            cp_async16(sB + dst, Bg + (size_t)r * KB + ch * 8);
        }
        CP_COMMIT();
    };

    float acc[2][8][4];
    #pragma unroll
    for (int mi = 0; mi < 2; mi++)
        #pragma unroll
        for (int ni = 0; ni < 8; ni++)
            #pragma unroll
            for (int q = 0; q < 4; q++) acc[mi][ni][q] = 0.f;

    load_chunk(0);
    load_chunk(1);

    for (int c = 0; c < nch; c++) {
        if (c + 1 < nch) { CP_WAIT(1); } else { CP_WAIT(0); }
        __syncthreads();

        const int buf = c & 1;
        const uint32_t sA = smu + buf * GBUF_B;
        const uint32_t sB = sA + GTILE_B;

        #pragma unroll
        for (int ks = 0; ks < GBK / 16; ks++) {
            uint32_t a[2][4];
            #pragma unroll
            for (int mi = 0; mi < 2; mi++) {
                int row = warp_m + mi * 16 + (lane & 15);
                int kc  = ks * 2 + (lane >> 4);
                uint32_t addr = sA + row * 128 + (((uint32_t)(kc ^ (row & 7))) << 4);
                ldsm4(a[mi], addr);
            }
            uint32_t bfr[4][4];
            #pragma unroll
            for (int nj = 0; nj < 4; nj++) {
                int row = warp_n + nj * 16 + (lane & 7) + ((lane >> 4) << 3);
                int kc  = ks * 2 + ((lane >> 3) & 1);
                uint32_t addr = sB + row * 128 + (((uint32_t)(kc ^ (row & 7))) << 4);
                ldsm4(bfr[nj], addr);
            }
            #pragma unroll
            for (int mi = 0; mi < 2; mi++)
                #pragma unroll
                for (int ni = 0; ni < 8; ni++) {
                    const uint32_t* bp = &bfr[ni >> 1][(ni & 1) * 2];
                    mma16816(acc[mi][ni], a[mi], bp[0], bp[1]);
                }
        }
        __syncthreads();
        if (c + 2 < nch) load_chunk(c + 2);
    }

    #pragma unroll
    for (int mi = 0; mi < 2; mi++) {
        int r0 = m0 + warp_m + mi * 16 + (lane >> 2);
        int r1 = r0 + 8;
        float* orow0 = nullptr;
        float* orow1 = nullptr;
        if (permute) {
            if (r0 < MROWS) {
                int bb = r0 & 31, tt = r0 >> 5;
                orow0 = C + (size_t)(bb * STEPS + tt) * N + n0;
            }
            if (r1 < MROWS) {
                int bb = r1 & 31, tt = r1 >> 5;
                orow1 = C + (size_t)(bb * STEPS + tt) * N + n0;
            }
        } else {
            orow0 = C + (size_t)r0 * N + n0;
            orow1 = C + (size_t)r1 * N + n0;
        }
        #pragma unroll
        for (int ni = 0; ni < 8; ni++) {
            int col = warp_n + ni * 8 + (lane & 3) * 2;
            float b0 = bias_s[col];
            float b1 = bias_s[col + 1];
            if (orow0) {
                float2 v; v.x = acc[mi][ni][0] + b0; v.y = acc[mi][ni][1] + b1;
                *(float2*)&orow0[col] = v;
            }
            if (orow1) {
                float2 v; v.x = acc[mi][ni][2] + b0; v.y = acc[mi][ni][3] + b1;
                *(float2*)&orow1[col] = v;
            }
        }
    }
}

// ---------------- persistent scan: 63 steps of one layer ----------------
// v3: double-buffered cp.async h staging — chunk c+1 prefetches while chunk c
// computes, hiding the L2 latency that round-12 exposed (2 syncs/chunk -> 1).
// Everything else identical to the round-12 passing kernel.
__global__ __launch_bounds__(128, 2)
void scan_kernel(const float* __restrict__ Wf, const float* __restrict__ Wi,
                 const float* __restrict__ Wo, const float* __restrict__ Wc,
                 const float* __restrict__ bfv, const float* __restrict__ biv,
                 const float* __restrict__ bov, const float* __restrict__ bcv,
                 const float* __restrict__ X, float* __restrict__ hT,
                 const float* __restrict__ c0T, int layer) {
    __shared__ float w_s[4][2][HIDDEN];                 // 16 KB
    __shared__ __align__(16) float h_s[2][64][BATCH];   // 16 KB double-buffered staging
    __shared__ float ex_s[4][2][BATCH];                 // 1 KB
    __shared__ float bias_s[4][2];

    const int tid = threadIdx.x;
    const int bid = blockIdx.x;
    const int b = tid & 31;
    const int q = tid >> 5;

    // load weight slice (h-part) into smem: rows (g, jj) = W_g[2*bid+jj][512:1024]
    #pragma unroll
    for (int pass = 0; pass < 8; pass++) {
        int g = pass >> 1, jj = pass & 1;
        const float* W = (g == 0) ? Wf : (g == 1) ? Wi : (g == 2) ? Wo : Wc;
        const float* src = W + (size_t)(2 * bid + jj) * 1024 + 512;
        *(float4*)&w_s[g][jj][tid * 4] = *(const float4*)&src[tid * 4];
    }
    if (tid < 8) {
        int g = tid >> 1, jj = tid & 1;
        const float* Bv = (g == 0) ? bfv : (g == 1) ? biv : (g == 2) ? bov : bcv;
        bias_s[g][jj] = Bv[2 * bid + jj];
    }
    float c_reg = 0.f;
    if (q < 2) c_reg = c0T[(2 * bid + q) * BATCH + b];
    __syncthreads();

    const unsigned G = gridDim.x;
    const unsigned per_ctr = G / NCTR;   // 32 arrivals per counter per step
    const uint32_t hs0 = smem_u32(&h_s[0][0][0]);

    // stage chunk cch of the h buffer hc into h_s[cch&1] (4 x cp.async16/thread)
    auto stage = [&](const float* hc, int cch) {
        const float4* src = (const float4*)hc + cch * 512;
        uint32_t dst = hs0 + (uint32_t)((cch & 1) * 8192);
        #pragma unroll
        for (int i = 0; i < 4; i++)
            cp_async16(dst + (i * 128 + tid) * 16, src + i * 128 + tid);
        CP_COMMIT();
    };

    // prefetch chunk 0 of step 0
    stage(hT + 0, 0);

    for (int t = 0; t < STEPS; t++) {
        const int p = t & 1;
        const float* hc = hT + p * (HIDDEN * BATCH);
        float* hn = hT + (p ^ 1) * (HIDDEN * BATCH);

        float acc0 = 0.f, acc1 = 0.f;
        for (int cch = 0; cch < 8; cch++) {
            CP_WAIT(0);
            __syncthreads();              // chunk cch landed; prior compute done
            if (cch < 7) stage(hc, cch + 1);

            const float (*hb)[BATCH] = h_s[cch & 1];
            const float* wa_base = &w_s[q][0][cch * 64];
            const float* wb_base = &w_s[q][1][cch * 64];
            #pragma unroll
            for (int k = 0; k < 64; k += 4) {
                float h0v = hb[k + 0][b];
                float h1v = hb[k + 1][b];
                float h2v = hb[k + 2][b];
                float h3v = hb[k + 3][b];
                float4 wa = *(const float4*)&wa_base[k];
                float4 wb = *(const float4*)&wb_base[k];
                acc0 += h0v * wa.x + h1v * wa.y + h2v * wa.z + h3v * wa.w;
                acc1 += h0v * wb.x + h1v * wb.y + h2v * wb.z + h3v * wb.w;
            }
        }
        float2 xr = *(const float2*)&X[(size_t)(t * BATCH + b) * GUNITS + q * 512 + 2 * bid];
        ex_s[q][0][b] = acc0 + bias_s[q][0] + xr.x;
        ex_s[q][1][b] = acc1 + bias_s[q][1] + xr.y;
        __syncthreads();

        if (q < 2) {
            float f  = sigmoidf_(ex_s[0][q][b]);
            float i  = sigmoidf_(ex_s[1][q][b]);
            float o  = sigmoidf_(ex_s[2][q][b]);
            float ct = tanhf    (ex_s[3][q][b]);
            c_reg = f * c_reg + i * ct;
            float h = o * tanhf(c_reg);
            int j = 2 * bid + q;
            hn[j * BATCH + b] = h;
            // fused convA: fp16 hi/lo split row for the downstream GEMM
            __half hhi = __float2half_rn(h);
            __half hlo = __float2half_rn(h - __half2float(hhi));
            size_t ab = (size_t)(t * BATCH + b) * KPA + j;
            g_A[ab]       = hhi;
            g_A[ab + 512] = hlo;
        }
        __syncthreads();

        // grid barrier v2: split counters
        if (tid == 0) {
            __threadfence();
            atomicAdd(&g_ctr[layer][(bid & (NCTR - 1)) * CTRPAD], 1u);
        }
        if (tid < NCTR) {
            unsigned target = (unsigned)(t + 1) * per_ctr;
            volatile unsigned* pc = &g_ctr[layer][tid * CTRPAD];
            while (*pc < target) { __nanosleep(32); }
            __threadfence();
        }
        __syncthreads();

        // prefetch chunk 0 of the next step (hn just became globally visible)
        if (t + 1 < STEPS) stage(hn, 0);
    }

    // reset counters for next launch/replay (last block to finish does it)
    if (tid == 0) {
        unsigned v = atomicAdd(&g_fin[layer], 1u);
        if (v == G - 1) {
            #pragma unroll
            for (int i = 0; i < NCTR; i++)
                g_ctr[layer][i * CTRPAD] = 0;
            g_fin[layer] = 0;
            __threadfence();
        }
    }
}

// ---------------- launch ----------------
extern "C" void kernel_launch(void* const* d_in, const int* in_sizes, int n_in,
                              void* d_out, int out_size) {
    const float* features = (const float*)d_in[0];
    const int*   captions = (const int*)  d_in[1];
    const float* embw     = (const float*)d_in[2];
    const float* Wf       = (const float*)d_in[3];
    const float* bf       = (const float*)d_in[4];
    const float* Wi       = (const float*)d_in[5];
    const float* bi       = (const float*)d_in[6];
    const float* Wc       = (const float*)d_in[7];
    const float* bc       = (const float*)d_in[8];
    const float* Wo       = (const float*)d_in[9];
    const float* bo       = (const float*)d_in[10];
    const float* out_w    = (const float*)d_in[11];
    const float* out_b    = (const float*)d_in[12];
    const float* ihw      = (const float*)d_in[13];
    const float* ihb      = (const float*)d_in[14];
    const float* icw      = (const float*)d_in[15];
    const float* icb      = (const float*)d_in[16];
    float* out = (float*)d_out;

    cudaFuncSetAttribute(gemm_split_kernel,
                         cudaFuncAttributeMaxDynamicSharedMemorySize, SMEM_DYN);

    __half* g_B_ptr;  cudaGetSymbolAddress((void**)&g_B_ptr,  g_B);
    __half* g_BW_ptr; cudaGetSymbolAddress((void**)&g_BW_ptr, g_BW);
    float*  g_X_ptr;  cudaGetSymbolAddress((void**)&g_X_ptr,  g_X);
    float*  g_hT0_p;  cudaGetSymbolAddress((void**)&g_hT0_p,  g_hT0);
    float*  g_hT1_p;  cudaGetSymbolAddress((void**)&g_hT1_p,  g_hT1);
    float*  g_c0T_p;  cudaGetSymbolAddress((void**)&g_c0T_p,  g_c0T);

    // 1. init state
    init_kernel<<<BATCH, 256>>>(features, ihw, ihb, icw, icb);

    // 2. conversions (weights; independent of recurrence)
    convB_kernel<<<(VOCAB * 512 / 4 + 255) / 256, 256>>>(out_w);
    convWx_kernel<<<(NLAYERS * GUNITS * 512 + 255) / 256, 256>>>(Wf, Wi, Wo, Wc);
    embA_kernel<<<(MROWS * 512 + 255) / 256, 256>>>(captions, embw);

    // 3. X0 = emb @ Wx0^T  (2-term: A=[hi|lo], B chunk wraps modulo 8)
    {
        dim3 grid(GUNITS / 128, MPAD / 128);  // 16 x 16
        gemm_split_kernel<<<grid, 256, SMEM_DYN>>>(g_BW_ptr, nullptr, g_X_ptr,
                                                   GUNITS, 0, 16, 8);
    }

    // 4. layer-0 scan (persistent; writes g_A hi/lo rows for X1)
    scan_kernel<<<SCAN_G, 128>>>(Wf, Wi, Wo, Wc, bf, bi, bo, bc,
                                 g_X_ptr, g_hT0_p, g_c0T_p, 0);

    // 5. X1 = h0 @ Wx1^T
    {
        dim3 grid(GUNITS / 128, MPAD / 128);
        gemm_split_kernel<<<grid, 256, SMEM_DYN>>>(g_BW_ptr + (size_t)GUNITS * KB,
                                                   nullptr, g_X_ptr, GUNITS, 0, 16, 8);
    }

    // 6. layer-1 scan (writes g_A hi/lo rows for logits)
    scan_kernel<<<SCAN_G, 128>>>(Wf + 512 * 1024, Wi + 512 * 1024,
                                 Wo + 512 * 1024, Wc + 512 * 1024,
                                 bf + 512, bi + 512, bo + 512, bc + 512,
                                 g_X_ptr, g_hT1_p, g_c0T_p, 1);

    // 7. logits = h1 @ out_w^T + out_b  (single-term fp16, permuted store)
    {
        dim3 grid(VOCAB / 128, MPAD / 128);   // 250 x 16
        gemm_split_kernel<<<grid, 256, SMEM_DYN>>>(g_B_ptr, out_b, out,
                                                   VOCAB, 1, 8, 8);
    }
}